// round 16
// baseline (speedup 1.0000x reference)
#include <cuda_runtime.h>
#include <cuda_fp16.h>
#include <math.h>

#define NN 20000
#define EE 640000
#define DD 64
#define CAP 128          // ELL capacity per dst node (mean in-degree 32; P(>128) ~ 0)
#define FULL 0xffffffffu
#define FXS 16777216.0f  // 2^24 fixed-point scale for packed degree

// ---------------- scratch ----------------
// g_pack is zero at every kernel_launch entry: statically zero-initialized,
// and final_fused_kernel re-zeroes it after its last (own-node) use each invocation.
// layout: [63:32] = in-count, [31:0] = sum(ew) in 2^-24 fixed point (max 2^31, no carry).
__device__ __align__(16) unsigned long long g_pack[NN];
__device__ __align__(16) int2   g_ell[NN * CAP]; // (src, weight-bits); conv2 folds dinv[src] in place
__device__ __align__(16) __half g_h1[NN * DD];   // fp16 storage, fp32 math
__device__ __align__(16) __half g_h2[NN * DD];

__device__ __forceinline__ float selu_f(float x) {
    const float sc = 1.0507009873554805f;
    const float al = 1.6732632423543772f;
    return x > 0.f ? sc * x : sc * al * (expf(x) - 1.f);
}

__device__ __forceinline__ void decode_pack(unsigned long long p, int& cnt, float& deg) {
    cnt = (int)(p >> 32);
    deg = (float)(unsigned)(p & 0xffffffffULL) * (1.0f / FXS);
}

// ---- fp16 vector helpers ----
__device__ __forceinline__ void st_h4(__half* p, float4 v) {
    uint2 u;
    __half2 a = __floats2half2_rn(v.x, v.y);
    __half2 b = __floats2half2_rn(v.z, v.w);
    u.x = *reinterpret_cast<unsigned*>(&a);
    u.y = *reinterpret_cast<unsigned*>(&b);
    *reinterpret_cast<uint2*>(p) = u;
}
__device__ __forceinline__ void ld_h8(const __half* p, float* v) {
    uint4 u = *reinterpret_cast<const uint4*>(p);
    __half2 h0 = *reinterpret_cast<__half2*>(&u.x);
    __half2 h1 = *reinterpret_cast<__half2*>(&u.y);
    __half2 h2 = *reinterpret_cast<__half2*>(&u.z);
    __half2 h3 = *reinterpret_cast<__half2*>(&u.w);
    float2 f0 = __half22float2(h0), f1 = __half22float2(h1);
    float2 f2 = __half22float2(h2), f3 = __half22float2(h3);
    v[0] = f0.x; v[1] = f0.y; v[2] = f1.x; v[3] = f1.y;
    v[4] = f2.x; v[5] = f2.y; v[6] = f3.x; v[7] = f3.y;
}

// ------- quarter-split ELL gather: each 8-lane quarter covers all 64 cols (fp16x8/lane); -------
// ------- quarters process different edges (4 edges per 16-edge step). -------
// FOLD=true: ELL weight is raw ew; fold dinv[src] on the fly and write back.
// Result (all lanes): a[i] = dinv_n * sum + dinv_n^2 * h[n], cols (lane&7)*8 + i.
template <bool FOLD>
__device__ __forceinline__ void gather8(const __half* __restrict__ hsrc,
                                        int n, int lane, float a[8]) {
    int cnt_all; float deg_n;
    decode_pack(g_pack[n], cnt_all, deg_n);
    int2* row = &g_ell[(size_t)n * CAP];
    int q = lane >> 3;            // quarter 0..3
    int coff = (lane & 7) * 8;    // fp16 element offset (16B aligned)
    float dinv_n = rsqrtf(1.f + deg_n);
    float hv[8];
    ld_h8(&hsrc[(size_t)n * DD + coff], hv);
    #pragma unroll
    for (int i = 0; i < 8; i++) a[i] = 0.f;
    for (int base = 0; base < cnt_all; base += 32) {
        int idx = base + lane;
        int sx = 0, wb = 0;
        if (idx < cnt_all) {
            int2 ed = row[idx];
            sx = ed.x;
            if (FOLD) {
                int cs; float ds;
                decode_pack(g_pack[sx], cs, ds);
                float wn = __int_as_float(ed.y) * rsqrtf(1.f + ds);
                wb = __float_as_int(wn);
                row[idx].y = wb;   // fold once; final gather reuses
            } else {
                wb = ed.y;
            }
        }
        int cnt = min(32, cnt_all - base);
        for (int k = 0; k < cnt; k += 16) {  // 16 edges/step; OOB lanes carry (0,0)
            int   s0 = __shfl_sync(FULL, sx, k + q);
            float w0 = __int_as_float(__shfl_sync(FULL, wb, k + q));
            int   s1 = __shfl_sync(FULL, sx, k + 4 + q);
            float w1 = __int_as_float(__shfl_sync(FULL, wb, k + 4 + q));
            int   s2 = __shfl_sync(FULL, sx, k + 8 + q);
            float w2 = __int_as_float(__shfl_sync(FULL, wb, k + 8 + q));
            int   s3 = __shfl_sync(FULL, sx, k + 12 + q);
            float w3 = __int_as_float(__shfl_sync(FULL, wb, k + 12 + q));
            float v0[8], v1[8], v2[8], v3[8];
            ld_h8(&hsrc[(size_t)s0 * DD + coff], v0);
            ld_h8(&hsrc[(size_t)s1 * DD + coff], v1);
            ld_h8(&hsrc[(size_t)s2 * DD + coff], v2);
            ld_h8(&hsrc[(size_t)s3 * DD + coff], v3);
            #pragma unroll
            for (int i = 0; i < 8; i++)
                a[i] += (w0 * v0[i] + w1 * v1[i]) + (w2 * v2[i] + w3 * v3[i]);
        }
    }
    #pragma unroll
    for (int i = 0; i < 8; i++) {
        a[i] += __shfl_xor_sync(FULL, a[i], 8);
        a[i] += __shfl_xor_sync(FULL, a[i], 16);
    }
    float self = dinv_n * dinv_n;
    #pragma unroll
    for (int i = 0; i < 8; i++) a[i] = dinv_n * a[i] + hv[i] * self;
}

// --------- warp matvec from SMEM weights (16-lane split, float4/lane) ---------
__device__ __forceinline__ void warp_matvec_s(const float* Wn,
                                              const float* xs, int lane, float acc[4]) {
    acc[0] = acc[1] = acc[2] = acc[3] = 0.f;
    int half_ = lane >> 4;
    int coff = (lane & 15) * 4;
    #pragma unroll
    for (int d = 0; d < DD; d += 2) {
        float4 w4 = *reinterpret_cast<const float4*>(&Wn[(d + half_) * DD + coff]);
        float xv = xs[d + half_];
        acc[0] += xv * w4.x; acc[1] += xv * w4.y;
        acc[2] += xv * w4.z; acc[3] += xv * w4.w;
    }
    #pragma unroll
    for (int c = 0; c < 4; c++)
        acc[c] += __shfl_xor_sync(FULL, acc[c], 16);
}

// --------- warp matvec from GLOBAL weights, streaming (evict-first) ---------
__device__ __forceinline__ void warp_matvec_cs(const float* __restrict__ Wn,
                                               const float* xs, int lane, float acc[4]) {
    acc[0] = acc[1] = acc[2] = acc[3] = 0.f;
    int half_ = lane >> 4;
    int coff = (lane & 15) * 4;
    #pragma unroll
    for (int d = 0; d < DD; d += 2) {
        float4 w4 = __ldcs(reinterpret_cast<const float4*>(&Wn[(d + half_) * DD + coff]));
        float xv = xs[d + half_];
        acc[0] += xv * w4.x; acc[1] += xv * w4.y;
        acc[2] += xv * w4.z; acc[3] += xv * w4.w;
    }
    #pragma unroll
    for (int c = 0; c < 4; c++)
        acc[c] += __shfl_xor_sync(FULL, acc[c], 16);
}

// -------- combo: 2 edges/thread + 2 matvecs/warp (16 nodes, 512 edges per block) --------
__global__ __launch_bounds__(256) void combo_kernel(const float* __restrict__ x,
                                                    const float* __restrict__ Wc,
                                                    const int* __restrict__ ei32,
                                                    const float* __restrict__ ew) {
    __shared__ float Ws[DD * DD];
    __shared__ float xs[16][DD];
    __shared__ int s_is64;
    int tid = threadIdx.x;

    if (tid < 32) {
        int ok = (ei32[2 * tid + 1] == 0) && (ei32[2 * (tid + 32) + 1] == 0);
        unsigned m = __ballot_sync(FULL, ok);
        if (tid == 0) s_is64 = (m == FULL);
    }

    #pragma unroll
    for (int i = tid; i < DD * DD; i += 256) Ws[i] = Wc[i];
    int w = tid >> 5, lane = tid & 31;
    int nodeA = blockIdx.x * 16 + w * 2;
    int nodeB = nodeA + 1;
    *reinterpret_cast<float2*>(&xs[w * 2][lane * 2]) =
        *reinterpret_cast<const float2*>(&x[(size_t)nodeA * DD + lane * 2]);
    *reinterpret_cast<float2*>(&xs[w * 2 + 1][lane * 2]) =
        *reinterpret_cast<const float2*>(&x[(size_t)nodeB * DD + lane * 2]);
    __syncthreads();

    int is64 = s_is64;
    int e0 = blockIdx.x * 512 + tid;
    int e1 = e0 + 256;
    int sA, dA, sB, dB;
    if (is64) {
        sA = __ldcs(&ei32[2 * e0]); dA = __ldcs(&ei32[2 * (EE + e0)]);
        sB = __ldcs(&ei32[2 * e1]); dB = __ldcs(&ei32[2 * (EE + e1)]);
    } else {
        sA = __ldcs(&ei32[e0]); dA = __ldcs(&ei32[EE + e0]);
        sB = __ldcs(&ei32[e1]); dB = __ldcs(&ei32[EE + e1]);
    }
    float wgtA = __ldcs(&ew[e0]);
    float wgtB = __ldcs(&ew[e1]);
    unsigned fxA = (unsigned)__float2uint_rn(wgtA * FXS);
    unsigned fxB = (unsigned)__float2uint_rn(wgtB * FXS);
    unsigned long long oldA =
        atomicAdd(&g_pack[dA], (1ULL << 32) | (unsigned long long)fxA);
    unsigned long long oldB =
        atomicAdd(&g_pack[dB], (1ULL << 32) | (unsigned long long)fxB);
    g_ell[dA * CAP + (int)(oldA >> 32)] = make_int2(sA, __float_as_int(wgtA));
    g_ell[dB * CAP + (int)(oldB >> 32)] = make_int2(sB, __float_as_int(wgtB));

    float acc[4];
    warp_matvec_s(Ws, xs[w * 2], lane, acc);
    if (lane < 16)
        st_h4(&g_h1[(size_t)nodeA * DD + (lane & 15) * 4],
              make_float4(acc[0], acc[1], acc[2], acc[3]));
    warp_matvec_s(Ws, xs[w * 2 + 1], lane, acc);
    if (lane < 16)
        st_h4(&g_h1[(size_t)nodeB * DD + (lane & 15) * 4],
              make_float4(acc[0], acc[1], acc[2], acc[3]));
}

// ---------------- conv2 fused: gather(h1, fold dinv_s) -> selu(+bc1) -> @Wc2 -> h2 ----------------
__global__ __launch_bounds__(256, 3) void conv2_fused_kernel(const float* __restrict__ Wc,
                                                             const float* __restrict__ bin) {
    __shared__ float Ws[DD * DD];
    __shared__ float xs[8][DD];
    int tid = threadIdx.x;
    #pragma unroll
    for (int i = tid; i < DD * DD; i += 256) Ws[i] = Wc[i];
    int w = tid >> 5, lane = tid & 31;
    int node = blockIdx.x * 8 + w;
    float a[8];
    gather8<true>(g_h1, node, lane, a);
    if (lane < 8) {
        int coff = lane * 8;
        float4 bi0 = *reinterpret_cast<const float4*>(&bin[coff]);
        float4 bi1 = *reinterpret_cast<const float4*>(&bin[coff + 4]);
        *reinterpret_cast<float4*>(&xs[w][coff]) =
            make_float4(selu_f(a[0] + bi0.x), selu_f(a[1] + bi0.y),
                        selu_f(a[2] + bi0.z), selu_f(a[3] + bi0.w));
        *reinterpret_cast<float4*>(&xs[w][coff + 4]) =
            make_float4(selu_f(a[4] + bi1.x), selu_f(a[5] + bi1.y),
                        selu_f(a[6] + bi1.z), selu_f(a[7] + bi1.w));
    }
    __syncthreads();
    float acc[4];
    warp_matvec_s(Ws, xs[w], lane, acc);
    if (lane < 16)
        st_h4(&g_h2[(size_t)node * DD + (lane & 15) * 4],
              make_float4(acc[0], acc[1], acc[2], acc[3]));
}

// ------- final fused: gather(h2) -> selu(+bc2) -> W1 -> LN -> W2 -> out; restore state -------
__global__ __launch_bounds__(256, 3) void final_fused_kernel(
        const float* __restrict__ bc2,
        const float* __restrict__ W1, const float* __restrict__ b1,
        const float* __restrict__ W2, const float* __restrict__ b2,
        const float* __restrict__ gam, const float* __restrict__ bet,
        float* __restrict__ out) {
    __shared__ float hs[8][DD];
    __shared__ float ts[8][DD];
    int tid = threadIdx.x;
    int w = tid >> 5, lane = tid & 31;
    int node = blockIdx.x * 8 + w;
    int coff4 = (lane & 15) * 4;

    float a[8];
    gather8<false>(g_h2, node, lane, a);
    // last use of g_pack (own node only in this kernel): restore zero for next replay
    if (lane == 0) g_pack[node] = 0ULL;
    if (lane < 8) {
        int coff = lane * 8;
        float4 bi0 = *reinterpret_cast<const float4*>(&bc2[coff]);
        float4 bi1 = *reinterpret_cast<const float4*>(&bc2[coff + 4]);
        *reinterpret_cast<float4*>(&hs[w][coff]) =
            make_float4(selu_f(a[0] + bi0.x), selu_f(a[1] + bi0.y),
                        selu_f(a[2] + bi0.z), selu_f(a[3] + bi0.w));
        *reinterpret_cast<float4*>(&hs[w][coff + 4]) =
            make_float4(selu_f(a[4] + bi1.x), selu_f(a[5] + bi1.y),
                        selu_f(a[6] + bi1.z), selu_f(a[7] + bi1.w));
    }
    __syncwarp();

    const float* W1n = W1 + (size_t)node * (DD * DD);
    float v[4];
    warp_matvec_cs(W1n, hs[w], lane, v);
    float4 b1v = __ldcs(reinterpret_cast<const float4*>(&b1[(size_t)node * DD + coff4]));
    v[0] += b1v.x; v[1] += b1v.y; v[2] += b1v.z; v[3] += b1v.w;

    // layernorm: each 16-lane half holds all 64 values (4 per lane)
    float s1 = v[0] + v[1] + v[2] + v[3];
    float s2 = v[0] * v[0] + v[1] * v[1] + v[2] * v[2] + v[3] * v[3];
    #pragma unroll
    for (int o = 8; o; o >>= 1) {
        s1 += __shfl_xor_sync(FULL, s1, o);
        s2 += __shfl_xor_sync(FULL, s2, o);
    }
    float mu  = s1 * (1.f / DD);
    float var = s2 * (1.f / DD) - mu * mu;
    float rstd = rsqrtf(var + 1e-5f);
    float4 gv = *reinterpret_cast<const float4*>(&gam[coff4]);
    float4 bv = *reinterpret_cast<const float4*>(&bet[coff4]);
    float t0 = (v[0] - mu) * rstd * gv.x + bv.x;
    float t1 = (v[1] - mu) * rstd * gv.y + bv.y;
    float t2 = (v[2] - mu) * rstd * gv.z + bv.z;
    float t3 = (v[3] - mu) * rstd * gv.w + bv.w;
    if (lane < 16)
        *reinterpret_cast<float4*>(&ts[w][coff4]) = make_float4(t0, t1, t2, t3);
    __syncwarp();

    const float* W2n = W2 + (size_t)node * (DD * DD);
    float q[4];
    warp_matvec_cs(W2n, ts[w], lane, q);
    if (lane < 16) {
        float4 b2v = __ldcs(reinterpret_cast<const float4*>(&b2[(size_t)node * DD + coff4]));
        float4 o = make_float4(q[0] + b2v.x, q[1] + b2v.y, q[2] + b2v.z, q[3] + b2v.w);
        *reinterpret_cast<float4*>(&out[(size_t)node * DD + coff4]) = o;
    }
}

// ---------------- launch: 3 kernels ----------------
extern "C" void kernel_launch(void* const* d_in, const int* in_sizes, int n_in,
                              void* d_out, int out_size) {
    const float* x   = (const float*)d_in[0];
    const int*   ei  = (const int*)d_in[1];
    const float* ew  = (const float*)d_in[2];
    const float* Wc1 = (const float*)d_in[3];
    const float* bc1 = (const float*)d_in[4];
    const float* Wc2 = (const float*)d_in[5];
    const float* bc2 = (const float*)d_in[6];
    const float* W1  = (const float*)d_in[7];
    const float* b1  = (const float*)d_in[8];
    const float* W2  = (const float*)d_in[9];
    const float* b2  = (const float*)d_in[10];
    const float* gam = (const float*)d_in[11];
    const float* bet = (const float*)d_in[12];
    float* out = (float*)d_out;

    combo_kernel<<<EE / 512, 256>>>(x, Wc1, ei, ew);
    conv2_fused_kernel<<<NN / 8, 256>>>(Wc2, bc1);
    final_fused_kernel<<<NN / 8, 256>>>(bc2, W1, b1, W2, b2, gam, bet, out);
}

// round 17
// speedup vs baseline: 1.0521x; 1.0521x over previous
#include <cuda_runtime.h>
#include <cuda_fp16.h>
#include <math.h>

#define NN 20000
#define EE 640000
#define DD 64
#define CAP 128          // ELL capacity per dst node (mean in-degree 32; P(>128) ~ 0)
#define FULL 0xffffffffu
#define FXS 16777216.0f  // 2^24 fixed-point scale for packed degree

// ---------------- scratch ----------------
// g_pack is zero at every kernel_launch entry: statically zero-initialized,
// and final_fused_kernel re-zeroes it after its last (own-node) use each invocation.
// layout: [63:32] = in-count, [31:0] = sum(ew) in 2^-24 fixed point (max 2^31, no carry).
__device__ __align__(16) unsigned long long g_pack[NN];
__device__ __align__(16) int2   g_ell[NN * CAP]; // (src, weight-bits); conv2 folds dinv[src] in place
__device__ __align__(16) __half g_h1[NN * DD];   // fp16 storage, fp32 math
__device__ __align__(16) __half g_h2[NN * DD];

__device__ __forceinline__ float selu_f(float x) {
    const float sc = 1.0507009873554805f;
    const float al = 1.6732632423543772f;
    return x > 0.f ? sc * x : sc * al * (expf(x) - 1.f);
}

__device__ __forceinline__ void decode_pack(unsigned long long p, int& cnt, float& deg) {
    cnt = (int)(p >> 32);
    deg = (float)(unsigned)(p & 0xffffffffULL) * (1.0f / FXS);
}

// ---- fp16x4 load/store helpers (8 bytes) ----
__device__ __forceinline__ float4 ld_h4(const __half* p) {
    uint2 u = *reinterpret_cast<const uint2*>(p);
    __half2 a = *reinterpret_cast<__half2*>(&u.x);
    __half2 b = *reinterpret_cast<__half2*>(&u.y);
    float2 fa = __half22float2(a), fb = __half22float2(b);
    return make_float4(fa.x, fa.y, fb.x, fb.y);
}
__device__ __forceinline__ void st_h4(__half* p, float4 v) {
    uint2 u;
    __half2 a = __floats2half2_rn(v.x, v.y);
    __half2 b = __floats2half2_rn(v.z, v.w);
    u.x = *reinterpret_cast<unsigned*>(&a);
    u.y = *reinterpret_cast<unsigned*>(&b);
    *reinterpret_cast<uint2*>(p) = u;
}

// ------- split-half ELL gather, 16 edges/iter (8 per half), fp16x4/lane. -------
// FOLD=true: ELL weight is raw ew; fold dinv[src] on the fly and write back.
// Returns dinv_n * sum + dinv_n^2 * h[n].
template <bool FOLD>
__device__ __forceinline__ float4 gather4(const __half* __restrict__ hsrc,
                                          int n, int lane) {
    int cnt_all; float deg_n;
    decode_pack(g_pack[n], cnt_all, deg_n);
    int2* row = &g_ell[(size_t)n * CAP];
    int half_ = lane >> 4;
    int coff = (lane & 15) * 4;
    float dinv_n = rsqrtf(1.f + deg_n);
    float4 hv = ld_h4(&hsrc[(size_t)n * DD + coff]);
    float a0 = 0.f, a1 = 0.f, a2 = 0.f, a3 = 0.f;
    for (int base = 0; base < cnt_all; base += 32) {
        int idx = base + lane;
        int sx = 0, wb = 0;
        if (idx < cnt_all) {
            int2 ed = row[idx];
            sx = ed.x;
            if (FOLD) {
                int c_s; float deg_s;
                decode_pack(g_pack[sx], c_s, deg_s);
                float wn = __int_as_float(ed.y) * rsqrtf(1.f + deg_s);
                wb = __float_as_int(wn);
                row[idx].y = wb;   // fold once; final gather reuses
            } else {
                wb = ed.y;
            }
        }
        int cnt = min(32, cnt_all - base);
        for (int k = 0; k < cnt; k += 16) {  // OOB shfl sources carry (0,0): harmless
            int   s0 = __shfl_sync(FULL, sx, k + half_);
            float w0 = __int_as_float(__shfl_sync(FULL, wb, k + half_));
            int   s1 = __shfl_sync(FULL, sx, k + 2 + half_);
            float w1 = __int_as_float(__shfl_sync(FULL, wb, k + 2 + half_));
            int   s2 = __shfl_sync(FULL, sx, k + 4 + half_);
            float w2 = __int_as_float(__shfl_sync(FULL, wb, k + 4 + half_));
            int   s3 = __shfl_sync(FULL, sx, k + 6 + half_);
            float w3 = __int_as_float(__shfl_sync(FULL, wb, k + 6 + half_));
            int   s4 = __shfl_sync(FULL, sx, k + 8 + half_);
            float w4 = __int_as_float(__shfl_sync(FULL, wb, k + 8 + half_));
            int   s5 = __shfl_sync(FULL, sx, k + 10 + half_);
            float w5 = __int_as_float(__shfl_sync(FULL, wb, k + 10 + half_));
            int   s6 = __shfl_sync(FULL, sx, k + 12 + half_);
            float w6 = __int_as_float(__shfl_sync(FULL, wb, k + 12 + half_));
            int   s7 = __shfl_sync(FULL, sx, k + 14 + half_);
            float w7 = __int_as_float(__shfl_sync(FULL, wb, k + 14 + half_));
            float4 v0 = ld_h4(&hsrc[(size_t)s0 * DD + coff]);
            float4 v1 = ld_h4(&hsrc[(size_t)s1 * DD + coff]);
            float4 v2 = ld_h4(&hsrc[(size_t)s2 * DD + coff]);
            float4 v3 = ld_h4(&hsrc[(size_t)s3 * DD + coff]);
            float4 v4 = ld_h4(&hsrc[(size_t)s4 * DD + coff]);
            float4 v5 = ld_h4(&hsrc[(size_t)s5 * DD + coff]);
            float4 v6 = ld_h4(&hsrc[(size_t)s6 * DD + coff]);
            float4 v7 = ld_h4(&hsrc[(size_t)s7 * DD + coff]);
            a0 += w0 * v0.x + w1 * v1.x;  a1 += w0 * v0.y + w1 * v1.y;
            a2 += w0 * v0.z + w1 * v1.z;  a3 += w0 * v0.w + w1 * v1.w;
            a0 += w2 * v2.x + w3 * v3.x;  a1 += w2 * v2.y + w3 * v3.y;
            a2 += w2 * v2.z + w3 * v3.z;  a3 += w2 * v2.w + w3 * v3.w;
            a0 += w4 * v4.x + w5 * v5.x;  a1 += w4 * v4.y + w5 * v5.y;
            a2 += w4 * v4.z + w5 * v5.z;  a3 += w4 * v4.w + w5 * v5.w;
            a0 += w6 * v6.x + w7 * v7.x;  a1 += w6 * v6.y + w7 * v7.y;
            a2 += w6 * v6.z + w7 * v7.z;  a3 += w6 * v6.w + w7 * v7.w;
        }
    }
    a0 += __shfl_xor_sync(FULL, a0, 16);
    a1 += __shfl_xor_sync(FULL, a1, 16);
    a2 += __shfl_xor_sync(FULL, a2, 16);
    a3 += __shfl_xor_sync(FULL, a3, 16);
    float self = dinv_n * dinv_n;
    return make_float4(dinv_n * a0 + hv.x * self, dinv_n * a1 + hv.y * self,
                       dinv_n * a2 + hv.z * self, dinv_n * a3 + hv.w * self);
}

// --------- warp matvec from SMEM weights ---------
__device__ __forceinline__ void warp_matvec_s(const float* Wn,
                                              const float* xs, int lane, float acc[4]) {
    acc[0] = acc[1] = acc[2] = acc[3] = 0.f;
    int half_ = lane >> 4;
    int coff = (lane & 15) * 4;
    #pragma unroll
    for (int d = 0; d < DD; d += 2) {
        float4 w4 = *reinterpret_cast<const float4*>(&Wn[(d + half_) * DD + coff]);
        float xv = xs[d + half_];
        acc[0] += xv * w4.x; acc[1] += xv * w4.y;
        acc[2] += xv * w4.z; acc[3] += xv * w4.w;
    }
    #pragma unroll
    for (int c = 0; c < 4; c++)
        acc[c] += __shfl_xor_sync(FULL, acc[c], 16);
}

// --------- warp matvec from GLOBAL weights, streaming (evict-first) ---------
__device__ __forceinline__ void warp_matvec_cs(const float* __restrict__ Wn,
                                               const float* xs, int lane, float acc[4]) {
    acc[0] = acc[1] = acc[2] = acc[3] = 0.f;
    int half_ = lane >> 4;
    int coff = (lane & 15) * 4;
    #pragma unroll
    for (int d = 0; d < DD; d += 2) {
        float4 w4 = __ldcs(reinterpret_cast<const float4*>(&Wn[(d + half_) * DD + coff]));
        float xv = xs[d + half_];
        acc[0] += xv * w4.x; acc[1] += xv * w4.y;
        acc[2] += xv * w4.z; acc[3] += xv * w4.w;
    }
    #pragma unroll
    for (int c = 0; c < 4; c++)
        acc[c] += __shfl_xor_sync(FULL, acc[c], 16);
}

// -------- combo: edge extraction + ELL placement AND conv1 lin (h1 = x @ Wc1) --------
// Edge LDGs hoisted above the staging barrier: their latency overlaps Ws/xs fill.
__global__ __launch_bounds__(256) void combo_kernel(const float* __restrict__ x,
                                                    const float* __restrict__ Wc,
                                                    const int* __restrict__ ei32,
                                                    const float* __restrict__ ew) {
    __shared__ float Ws[DD * DD];
    __shared__ float xs[8][DD];
    __shared__ int s_is64;
    int tid = threadIdx.x;

    if (tid < 32) {
        int ok = (ei32[2 * tid + 1] == 0) && (ei32[2 * (tid + 32) + 1] == 0);
        unsigned m = __ballot_sync(FULL, ok);
        if (tid == 0) s_is64 = (m == FULL);
    }
    __syncthreads();          // s_is64 visible
    int is64 = s_is64;

    // issue the 3 edge loads FIRST — latency drains under the staging below
    int e = blockIdx.x * 256 + tid;
    int s, d;
    if (is64) { s = __ldcs(&ei32[2 * e]); d = __ldcs(&ei32[2 * (EE + e)]); }
    else      { s = __ldcs(&ei32[e]);     d = __ldcs(&ei32[EE + e]); }
    float wgt = __ldcs(&ew[e]);

    #pragma unroll
    for (int i = tid; i < DD * DD; i += 256) Ws[i] = Wc[i];
    int w = tid >> 5, lane = tid & 31;
    int node = blockIdx.x * 8 + w;
    *reinterpret_cast<float2*>(&xs[w][lane * 2]) =
        *reinterpret_cast<const float2*>(&x[(size_t)node * DD + lane * 2]);

    // single packed atomic: count in high 32, fixed-point degree in low 32
    unsigned fx = (unsigned)__float2uint_rn(wgt * FXS);
    unsigned long long old =
        atomicAdd(&g_pack[d], (1ULL << 32) | (unsigned long long)fx);
    int rank = (int)(old >> 32);
    g_ell[d * CAP + rank] = make_int2(s, __float_as_int(wgt));

    __syncthreads();

    float acc[4];
    warp_matvec_s(Ws, xs[w], lane, acc);
    if (lane < 16)
        st_h4(&g_h1[(size_t)node * DD + (lane & 15) * 4],
              make_float4(acc[0], acc[1], acc[2], acc[3]));
}

// ---------------- conv2 fused: gather(h1, fold dinv_s) -> selu(+bc1) -> @Wc2 -> h2 ----------------
__global__ __launch_bounds__(256, 4) void conv2_fused_kernel(const float* __restrict__ Wc,
                                                             const float* __restrict__ bin) {
    __shared__ float Ws[DD * DD];
    __shared__ float xs[8][DD];
    int tid = threadIdx.x;
    #pragma unroll
    for (int i = tid; i < DD * DD; i += 256) Ws[i] = Wc[i];
    int w = tid >> 5, lane = tid & 31;
    int node = blockIdx.x * 8 + w;
    int coff = (lane & 15) * 4;
    float4 a = gather4<true>(g_h1, node, lane);
    if (lane < 16) {
        float4 bi = *reinterpret_cast<const float4*>(&bin[coff]);
        float4 sv = make_float4(selu_f(a.x + bi.x), selu_f(a.y + bi.y),
                                selu_f(a.z + bi.z), selu_f(a.w + bi.w));
        *reinterpret_cast<float4*>(&xs[w][coff]) = sv;
    }
    __syncthreads();
    float acc[4];
    warp_matvec_s(Ws, xs[w], lane, acc);
    if (lane < 16)
        st_h4(&g_h2[(size_t)node * DD + coff],
              make_float4(acc[0], acc[1], acc[2], acc[3]));
}

// ------- final fused: gather(h2) -> selu(+bc2) -> W1 -> LN -> W2 -> out; restore state -------
__global__ __launch_bounds__(256, 4) void final_fused_kernel(
        const float* __restrict__ bc2,
        const float* __restrict__ W1, const float* __restrict__ b1,
        const float* __restrict__ W2, const float* __restrict__ b2,
        const float* __restrict__ gam, const float* __restrict__ bet,
        float* __restrict__ out) {
    __shared__ float hs[8][DD];
    __shared__ float ts[8][DD];
    int tid = threadIdx.x;
    int w = tid >> 5, lane = tid & 31;
    int node = blockIdx.x * 8 + w;
    int coff = (lane & 15) * 4;

    float4 a = gather4<false>(g_h2, node, lane);
    // last use of g_pack (own node only in this kernel): restore zero for next replay
    if (lane == 0) g_pack[node] = 0ULL;
    if (lane < 16) {
        float4 bi = *reinterpret_cast<const float4*>(&bc2[coff]);
        float4 sv = make_float4(selu_f(a.x + bi.x), selu_f(a.y + bi.y),
                                selu_f(a.z + bi.z), selu_f(a.w + bi.w));
        *reinterpret_cast<float4*>(&hs[w][coff]) = sv;
    }
    __syncwarp();

    const float* W1n = W1 + (size_t)node * (DD * DD);
    float v[4];
    warp_matvec_cs(W1n, hs[w], lane, v);
    float4 b1v = __ldcs(reinterpret_cast<const float4*>(&b1[(size_t)node * DD + coff]));
    v[0] += b1v.x; v[1] += b1v.y; v[2] += b1v.z; v[3] += b1v.w;

    // layernorm: each 16-lane half holds all 64 values (4 per lane)
    float s1 = v[0] + v[1] + v[2] + v[3];
    float s2 = v[0] * v[0] + v[1] * v[1] + v[2] * v[2] + v[3] * v[3];
    #pragma unroll
    for (int o = 8; o; o >>= 1) {
        s1 += __shfl_xor_sync(FULL, s1, o);
        s2 += __shfl_xor_sync(FULL, s2, o);
    }
    float mu  = s1 * (1.f / DD);
    float var = s2 * (1.f / DD) - mu * mu;
    float rstd = rsqrtf(var + 1e-5f);
    float4 gv = *reinterpret_cast<const float4*>(&gam[coff]);
    float4 bv = *reinterpret_cast<const float4*>(&bet[coff]);
    float t0 = (v[0] - mu) * rstd * gv.x + bv.x;
    float t1 = (v[1] - mu) * rstd * gv.y + bv.y;
    float t2 = (v[2] - mu) * rstd * gv.z + bv.z;
    float t3 = (v[3] - mu) * rstd * gv.w + bv.w;
    if (lane < 16)
        *reinterpret_cast<float4*>(&ts[w][coff]) = make_float4(t0, t1, t2, t3);
    __syncwarp();

    const float* W2n = W2 + (size_t)node * (DD * DD);
    float q[4];
    warp_matvec_cs(W2n, ts[w], lane, q);
    if (lane < 16) {
        float4 b2v = __ldcs(reinterpret_cast<const float4*>(&b2[(size_t)node * DD + coff]));
        float4 o = make_float4(q[0] + b2v.x, q[1] + b2v.y, q[2] + b2v.z, q[3] + b2v.w);
        *reinterpret_cast<float4*>(&out[(size_t)node * DD + coff]) = o;
    }
}

// ---------------- launch: 3 kernels ----------------
extern "C" void kernel_launch(void* const* d_in, const int* in_sizes, int n_in,
                              void* d_out, int out_size) {
    const float* x   = (const float*)d_in[0];
    const int*   ei  = (const int*)d_in[1];
    const float* ew  = (const float*)d_in[2];
    const float* Wc1 = (const float*)d_in[3];
    const float* bc1 = (const float*)d_in[4];
    const float* Wc2 = (const float*)d_in[5];
    const float* bc2 = (const float*)d_in[6];
    const float* W1  = (const float*)d_in[7];
    const float* b1  = (const float*)d_in[8];
    const float* W2  = (const float*)d_in[9];
    const float* b2  = (const float*)d_in[10];
    const float* gam = (const float*)d_in[11];
    const float* bet = (const float*)d_in[12];
    float* out = (float*)d_out;

    combo_kernel<<<EE / 256, 256>>>(x, Wc1, ei, ew);
    conv2_fused_kernel<<<NN / 8, 256>>>(Wc2, bc1);
    final_fused_kernel<<<NN / 8, 256>>>(bc2, W1, b1, W2, b2, gam, bet, out);
}